// round 15
// baseline (speedup 1.0000x reference)
#include <cuda_runtime.h>
#include <cuda_fp16.h>
#include <math.h>
#include <stdint.h>

// Problem constants
#define BB   2
#define SS   2048
#define DD   1024
#define HH   16
#define HDIM 64
#define MM   (BB*SS)          // 4096 rows
#define RMS_EPS 1e-8f

// Scratch (fp16 on the tensor path)
__device__ __half g_xh[MM*DD];          // hidden in fp16
__device__ __half g_wqh[DD*DD];
__device__ __half g_wkh[DD*DD];
__device__ __half g_wvh[DD*DD];
__device__ __half g_woh[DD*DD];
__device__ __half g_qh[BB*HH*SS*HDIM];  // [B,H,S,HD], pre-scaled by 0.125*log2e
__device__ __half g_kh[BB*HH*SS*HDIM];  // [B,H,S,HD]
__device__ __half g_vh[BB*HH*SS*HDIM];  // [B,H,S,HD]
__device__ __half g_ctxh[MM*DD];        // [B,S,D]
__device__ float g_x[MM*DD];            // post-proj + residual (fp32)

// ---------------------------------------------------------------------------
// helpers
// ---------------------------------------------------------------------------
__device__ __forceinline__ uint32_t smem_u32(const void* p) {
    uint32_t a;
    asm("{ .reg .u64 t; cvta.to.shared.u64 t, %1; cvt.u32.u64 %0, t; }"
        : "=r"(a) : "l"(p));
    return a;
}

// D += A(16x16) * B(16x8), fp16 inputs, fp32 accum
__device__ __forceinline__ void mma_f16(float* d, const uint32_t* a, const uint32_t* b) {
    asm volatile(
        "mma.sync.aligned.m16n8k16.row.col.f32.f16.f16.f32 "
        "{%0,%1,%2,%3}, {%4,%5,%6,%7}, {%8,%9}, {%0,%1,%2,%3};"
        : "+f"(d[0]), "+f"(d[1]), "+f"(d[2]), "+f"(d[3])
        : "r"(a[0]), "r"(a[1]), "r"(a[2]), "r"(a[3]), "r"(b[0]), "r"(b[1]));
}

// D += A(16x16) * B(16x8), fp16 inputs, fp16 accum (packed, 2 regs)
__device__ __forceinline__ void mma_f16h(uint32_t* d, const uint32_t* a, const uint32_t* b) {
    asm volatile(
        "mma.sync.aligned.m16n8k16.row.col.f16.f16.f16.f16 "
        "{%0,%1}, {%2,%3,%4,%5}, {%6,%7}, {%0,%1};"
        : "+r"(d[0]), "+r"(d[1])
        : "r"(a[0]), "r"(a[1]), "r"(a[2]), "r"(a[3]), "r"(b[0]), "r"(b[1]));
}

#define LDMX4(r0, r1, r2, r3, addr) \
    asm volatile("ldmatrix.sync.aligned.m8n8.x4.shared.b16 {%0,%1,%2,%3}, [%4];" \
                 : "=r"(r0), "=r"(r1), "=r"(r2), "=r"(r3) : "r"(addr))

#define LDMX4T(r0, r1, r2, r3, addr) \
    asm volatile("ldmatrix.sync.aligned.m8n8.x4.trans.shared.b16 {%0,%1,%2,%3}, [%4];" \
                 : "=r"(r0), "=r"(r1), "=r"(r2), "=r"(r3) : "r"(addr))

#define CP_ASYNC16(saddr, gptr) \
    asm volatile("cp.async.cg.shared.global [%0], [%1], 16;" :: "r"(saddr), "l"(gptr))
#define CP_COMMIT() asm volatile("cp.async.commit_group;")
#define CP_WAIT(N)  asm volatile("cp.async.wait_group %0;" :: "n"(N))

__device__ __forceinline__ uint32_t pack_h16(float x, float y) {
    __half2 p = __floats2half2_rn(x, y);
    return *reinterpret_cast<uint32_t*>(&p);
}

__device__ __forceinline__ uint32_t hmax2(uint32_t a, uint32_t b) {
    uint32_t r;
    asm("max.f16x2 %0, %1, %2;" : "=r"(r) : "r"(a), "r"(b));
    return r;
}
__device__ __forceinline__ uint32_t hsub2_ex2(uint32_t a, uint32_t m2) {
    uint32_t d, r;
    asm("sub.f16x2 %0, %1, %2;" : "=r"(d) : "r"(a), "r"(m2));
    asm("ex2.approx.f16x2 %0, %1;" : "=r"(r) : "r"(d));
    return r;
}
__device__ __forceinline__ float hmax_pair_to_f32(uint32_t h) {
    __half2 v = *reinterpret_cast<__half2*>(&h);
    return fmaxf(__half2float(__low2half(v)), __half2float(__high2half(v)));
}

#define ONES_H2 0x3C003C00u   // fp16 {1.0, 1.0}

// ---------------------------------------------------------------------------
// Kernel 0: fp32 -> fp16 conversion prepass
// ---------------------------------------------------------------------------
__global__ __launch_bounds__(256) void cvt_h_kernel(const float4* __restrict__ src)
{
    int i = blockIdx.x * 256 + threadIdx.x;
    if (i < MM * DD / 4) {
        float4 v = src[i];
        uint2 o;
        o.x = pack_h16(v.x, v.y);
        o.y = pack_h16(v.z, v.w);
        reinterpret_cast<uint2*>(g_xh)[i] = o;
    }
}

__global__ __launch_bounds__(256) void cvt_w_kernel(
    const float4* __restrict__ wq, const float4* __restrict__ wk,
    const float4* __restrict__ wv, const float4* __restrict__ wo)
{
    int i = blockIdx.x * 256 + threadIdx.x;
    if (i >= DD * DD / 4) return;
    int z = blockIdx.y;
    const float4* s = (z == 0) ? wq : (z == 1) ? wk : (z == 2) ? wv : wo;
    __half* dp = (z == 0) ? g_wqh : (z == 1) ? g_wkh : (z == 2) ? g_wvh : g_woh;
    float4 v = s[i];
    uint2 o;
    o.x = pack_h16(v.x, v.y);
    o.y = pack_h16(v.z, v.w);
    reinterpret_cast<uint2*>(dp)[i] = o;
}

// ---------------------------------------------------------------------------
// fp16 GEMM mainloop: 128x128 tile, 4 warps, warp tile 64x64 (unchanged)
// ---------------------------------------------------------------------------
#define KCB   32
#define SAB   40
#define TILEB (128 * SAB)

__device__ __forceinline__ void gemm_mainloop_f16(
    float (&acc)[4][8][4],
    const __half* __restrict__ A, const __half* __restrict__ W,
    int m0, int n0, __half* As, __half* Bs)
{
    const int tid  = threadIdx.x;
    const int wid  = tid >> 5, lane = tid & 31;
    const int wm = wid & 1, wn = wid >> 1;

    const uint32_t as_base = smem_u32(As);
    const uint32_t bs_base = smem_u32(Bs);

    uint32_t a_off[4], b_off[4];
#pragma unroll
    for (int mi = 0; mi < 4; mi++)
        a_off[mi] = (uint32_t)(((wm * 64 + mi * 16 + (lane & 15)) * SAB + (lane >> 4) * 8) * 2);
#pragma unroll
    for (int nip = 0; nip < 4; nip++)
        b_off[nip] = (uint32_t)(((wn * 64 + nip * 16 + (lane & 7) + ((lane >> 4) & 1) * 8) * SAB
                                 + ((lane >> 3) & 1) * 8) * 2);

#pragma unroll
    for (int mi = 0; mi < 4; mi++)
#pragma unroll
        for (int ni = 0; ni < 8; ni++)
#pragma unroll
            for (int c = 0; c < 4; c++) acc[mi][ni][c] = 0.f;

    auto issue = [&](int buf, int k0) {
#pragma unroll
        for (int r = 0; r < 4; r++) {
            int idx = tid + (r << 7);
            int row = idx >> 2, c = idx & 3;
            uint32_t soff = (uint32_t)((buf * TILEB + row * SAB) * 2 + c * 16);
            const char* ga = (const char*)(A + (size_t)(m0 + row) * DD + k0) + c * 16;
            const char* gb = (const char*)(W + (size_t)(n0 + row) * DD + k0) + c * 16;
            CP_ASYNC16(as_base + soff, ga);
            CP_ASYNC16(bs_base + soff, gb);
        }
        CP_COMMIT();
    };

    issue(0, 0);
    for (int k0 = 0; k0 < DD; k0 += KCB) {
        int buf = (k0 / KCB) & 1;
        bool has_next = (k0 + KCB) < DD;
        if (has_next) {
            issue(buf ^ 1, k0 + KCB);
            CP_WAIT(1);
        } else {
            CP_WAIT(0);
        }
        __syncthreads();

        uint32_t abase = as_base + (uint32_t)(buf * TILEB * 2);
        uint32_t bbase = bs_base + (uint32_t)(buf * TILEB * 2);
#pragma unroll
        for (int ks = 0; ks < KCB; ks += 16) {
            uint32_t af[4][4], bf[8][2];
#pragma unroll
            for (int mi = 0; mi < 4; mi++)
                LDMX4(af[mi][0], af[mi][1], af[mi][2], af[mi][3],
                      abase + a_off[mi] + ks * 2);
#pragma unroll
            for (int nip = 0; nip < 4; nip++)
                LDMX4(bf[2 * nip][0], bf[2 * nip][1], bf[2 * nip + 1][0], bf[2 * nip + 1][1],
                      bbase + b_off[nip] + ks * 2);
#pragma unroll
            for (int mi = 0; mi < 4; mi++)
#pragma unroll
                for (int ni = 0; ni < 8; ni++)
                    mma_f16(acc[mi][ni], af[mi], bf[ni]);
        }
        __syncthreads();
    }
}

// ---------------------------------------------------------------------------
// Kernel 1: QKV projection + RoPE + scatter to [B,H,S,HD]
// ---------------------------------------------------------------------------
__global__ __launch_bounds__(128) void qkv_rope_mma_kernel(
    const float* __restrict__ sinb, const float* __restrict__ cosb)
{
    __shared__ __half As[2 * TILEB];
    __shared__ __half Bs[2 * TILEB];

    const int m0 = blockIdx.y << 7;
    const int n0 = blockIdx.x << 7;
    const int z  = blockIdx.z;
    const __half* W = (z == 0) ? g_wqh : (z == 1 ? g_wkh : g_wvh);
    __half* outp    = (z == 0) ? g_qh  : (z == 1 ? g_kh  : g_vh);

    float acc[4][8][4];
    gemm_mainloop_f16(acc, g_xh, W, m0, n0, As, Bs);

    const int tid = threadIdx.x, wid = tid >> 5, lane = tid & 31;
    const int wm = wid & 1, wn = wid >> 1;
    const int gid = lane >> 2, tig = lane & 3;
    const float qs = (z == 0) ? 0.125f * 1.44269504088896f : 1.0f;

#pragma unroll
    for (int mi = 0; mi < 4; mi++) {
#pragma unroll
        for (int half = 0; half < 2; half++) {
            int m  = m0 + wm * 64 + mi * 16 + gid + half * 8;
            int bb = m >> 11;
            int s  = m & (SS - 1);
#pragma unroll
            for (int ni = 0; ni < 8; ni++) {
                int n  = n0 + wn * 64 + ni * 8 + 2 * tig;
                int h  = n >> 6;
                int hd = n & 63;
                int ir = hd >> 1;
                float sn = sinb[s * (HDIM / 2) + ir];
                float cs = cosb[s * (HDIM / 2) + ir];
                float x1 = acc[mi][ni][half * 2 + 0];
                float x2 = acc[mi][ni][half * 2 + 1];
                float o1 = (x1 * cs - x2 * sn) * qs;
                float o2 = (x2 * cs + x1 * sn) * qs;
                size_t base = ((size_t)(bb * HH + h) * SS + s) * HDIM + hd;
                *reinterpret_cast<uint32_t*>(&outp[base]) = pack_h16(o1, o2);
            }
        }
    }
}

// ---------------------------------------------------------------------------
// Kernel 3: O-proj + bias + residual -> g_x (fp32)
// ---------------------------------------------------------------------------
__global__ __launch_bounds__(128) void oproj_mma_kernel(
    const float* __restrict__ hidden, const float* __restrict__ bo)
{
    __shared__ __half As[2 * TILEB];
    __shared__ __half Bs[2 * TILEB];

    const int m0 = blockIdx.y << 7;
    const int n0 = blockIdx.x << 7;

    float acc[4][8][4];
    gemm_mainloop_f16(acc, g_ctxh, g_woh, m0, n0, As, Bs);

    const int tid = threadIdx.x, wid = tid >> 5, lane = tid & 31;
    const int wm = wid & 1, wn = wid >> 1;
    const int gid = lane >> 2, tig = lane & 3;

#pragma unroll
    for (int mi = 0; mi < 4; mi++) {
#pragma unroll
        for (int half = 0; half < 2; half++) {
            int m = m0 + wm * 64 + mi * 16 + gid + half * 8;
#pragma unroll
            for (int ni = 0; ni < 8; ni++) {
                int n = n0 + wn * 64 + ni * 8 + 2 * tig;
                float2 hv = *reinterpret_cast<const float2*>(&hidden[(size_t)m * DD + n]);
                float2 bv = *reinterpret_cast<const float2*>(&bo[n]);
                float2 o;
                o.x = acc[mi][ni][half * 2 + 0] + bv.x + hv.x;
                o.y = acc[mi][ni][half * 2 + 1] + bv.y + hv.y;
                *reinterpret_cast<float2*>(&g_x[(size_t)m * DD + n]) = o;
            }
        }
    }
}

// ---------------------------------------------------------------------------
// Kernel 2: flash attention — QK^T fp16 accum, f16x2 softmax, PV fp32 accum.
// __launch_bounds__(128, 3): cap regs at 166 so 3 CTAs/SM co-reside and
// cover each other's softmax phases (phase-stagger latency hiding).
// ---------------------------------------------------------------------------
#define KSTRB 72
#define AT_TILE (64 * KSTRB)

__global__ __launch_bounds__(128, 3) void attn_mma_kernel()
{
    __shared__ __half Ks[2 * AT_TILE];
    __shared__ __half Vs[2 * AT_TILE];

    const int tid = threadIdx.x, wid = tid >> 5, lane = tid & 31;
    const int gid = lane >> 2, tig = lane & 3;
    const int q0 = blockIdx.x << 7;
    const int bh = blockIdx.y;
    const __half* qp = g_qh + (size_t)bh * SS * HDIM;
    const __half* kp = g_kh + (size_t)bh * SS * HDIM;
    const __half* vp = g_vh + (size_t)bh * SS * HDIM;

    const uint32_t ks_base = smem_u32(Ks);
    const uint32_t vs_base = smem_u32(Vs);

    uint32_t ap_off[2];
#pragma unroll
    for (int b = 0; b < 2; b++)
        ap_off[b] = (uint32_t)(((wid * 32 + b * 16 + (lane & 15)) * KSTRB + (lane >> 4) * 8) * 2);
    const uint32_t kb_off = (uint32_t)((((lane & 7) + ((lane >> 4) & 1) * 8) * KSTRB
                                        + ((lane >> 3) & 1) * 8) * 2);
    const uint32_t vt_off = (uint32_t)(((lane & 15) * KSTRB + ((lane >> 4) & 1) * 8) * 2);

    // stage Q tile through Ks, grab frags
#pragma unroll
    for (int r = 0; r < 8; r++) {
        int idx = tid + (r << 7);
        int row = idx >> 3, c = idx & 7;
        *reinterpret_cast<uint4*>(&Ks[row * KSTRB + c * 8]) =
            *reinterpret_cast<const uint4*>(&qp[(size_t)(q0 + row) * HDIM + c * 8]);
    }
    __syncthreads();

    uint32_t qf[2][4][4];
#pragma unroll
    for (int b = 0; b < 2; b++)
#pragma unroll
        for (int kk = 0; kk < 4; kk++)
            LDMX4(qf[b][kk][0], qf[b][kk][1], qf[b][kk][2], qf[b][kk][3],
                  ks_base + ap_off[b] + kk * 32);
    __syncthreads();

    float oacc[2][8][4];
#pragma unroll
    for (int b = 0; b < 2; b++)
#pragma unroll
        for (int ni = 0; ni < 8; ni++)
#pragma unroll
            for (int c = 0; c < 4; c++) oacc[b][ni][c] = 0.f;
    float mrow[2][2] = {{-1e30f, -1e30f}, {-1e30f, -1e30f}};
    float lacc[2][4] = {{0.f, 0.f, 0.f, 0.f}, {0.f, 0.f, 0.f, 0.f}};
    const uint32_t onesb[2] = {ONES_H2, ONES_H2};

    auto issue = [&](int buf, int kt) {
#pragma unroll
        for (int r = 0; r < 4; r++) {
            int c = tid + (r << 7);
            int row = c >> 3, col = (c & 7) * 8;
            uint32_t so = (uint32_t)(((buf * 64 + row) * KSTRB + col) * 2);
            CP_ASYNC16(ks_base + so, kp + (size_t)(kt + row) * HDIM + col);
            CP_ASYNC16(vs_base + so, vp + (size_t)(kt + row) * HDIM + col);
        }
        CP_COMMIT();
    };

    issue(0, 0);
    for (int t = 0; t < SS / 64; t++) {
        int buf = t & 1;
        if (t + 1 < SS / 64) {
            issue(buf ^ 1, (t + 1) * 64);
            CP_WAIT(1);
        } else {
            CP_WAIT(0);
        }
        __syncthreads();

        uint32_t kb = ks_base + (uint32_t)(buf * AT_TILE * 2);
        uint32_t vb = vs_base + (uint32_t)(buf * AT_TILE * 2);

        // S = Q K^T (fp16 accum, packed: [0]=row gid, [1]=row gid+8)
        uint32_t sacc[2][8][2];
#pragma unroll
        for (int b = 0; b < 2; b++)
#pragma unroll
            for (int ni = 0; ni < 8; ni++) {
                sacc[b][ni][0] = 0u; sacc[b][ni][1] = 0u;
            }

#pragma unroll
        for (int kk = 0; kk < 4; kk++) {
            uint32_t kf[8][2];
#pragma unroll
            for (int nip = 0; nip < 4; nip++)
                LDMX4(kf[2 * nip][0], kf[2 * nip][1], kf[2 * nip + 1][0], kf[2 * nip + 1][1],
                      kb + kb_off + (uint32_t)(nip * 16 * KSTRB * 2) + kk * 32);
#pragma unroll
            for (int ni = 0; ni < 8; ni++) {
                mma_f16h(sacc[0][ni], qf[0][kk], kf[ni]);
                mma_f16h(sacc[1][ni], qf[1][kk], kf[ni]);
            }
        }

        // softmax in f16x2: max -> sub+ex2 in place (sacc becomes P frags)
#pragma unroll
        for (int b = 0; b < 2; b++) {
            uint32_t pm0 = sacc[b][0][0], pm1 = sacc[b][0][1];
#pragma unroll
            for (int ni = 1; ni < 8; ni++) {
                pm0 = hmax2(pm0, sacc[b][ni][0]);
                pm1 = hmax2(pm1, sacc[b][ni][1]);
            }
            float mx0 = hmax_pair_to_f32(pm0);
            float mx1 = hmax_pair_to_f32(pm1);
#pragma unroll
            for (int off = 1; off <= 2; off <<= 1) {
                mx0 = fmaxf(mx0, __shfl_xor_sync(0xffffffffu, mx0, off));
                mx1 = fmaxf(mx1, __shfl_xor_sync(0xffffffffu, mx1, off));
            }
            float mn0 = fmaxf(mrow[b][0], mx0), mn1 = fmaxf(mrow[b][1], mx1);
            float corr0 = exp2f(mrow[b][0] - mn0), corr1 = exp2f(mrow[b][1] - mn1);
            mrow[b][0] = mn0; mrow[b][1] = mn1;
            uint32_t m20 = pack_h16(mn0, mn0);
            uint32_t m21 = pack_h16(mn1, mn1);
#pragma unroll
            for (int ni = 0; ni < 8; ni++) {
                sacc[b][ni][0] = hsub2_ex2(sacc[b][ni][0], m20);
                sacc[b][ni][1] = hsub2_ex2(sacc[b][ni][1], m21);
            }
            lacc[b][0] *= corr0; lacc[b][1] *= corr0;
            lacc[b][2] *= corr1; lacc[b][3] *= corr1;
#pragma unroll
            for (int ni = 0; ni < 8; ni++) {
                oacc[b][ni][0] *= corr0; oacc[b][ni][1] *= corr0;
                oacc[b][ni][2] *= corr1; oacc[b][ni][3] *= corr1;
            }
        }

        // O += P V; l += P @ 1.  P A-frags come straight from sacc.
#pragma unroll
        for (int kk = 0; kk < 4; kk++) {
            uint32_t vf[8][2];
#pragma unroll
            for (int nip = 0; nip < 4; nip++)
                LDMX4T(vf[2 * nip][0], vf[2 * nip][1], vf[2 * nip + 1][0], vf[2 * nip + 1][1],
                       vb + vt_off + (uint32_t)((kk * 16 * KSTRB + nip * 16) * 2));
#pragma unroll
            for (int b = 0; b < 2; b++) {
                uint32_t pf[4];
                pf[0] = sacc[b][2 * kk][0];
                pf[1] = sacc[b][2 * kk][1];
                pf[2] = sacc[b][2 * kk + 1][0];
                pf[3] = sacc[b][2 * kk + 1][1];
#pragma unroll
                for (int ni = 0; ni < 8; ni++)
                    mma_f16(oacc[b][ni], pf, vf[ni]);
                mma_f16(lacc[b], pf, onesb);
            }
        }
        __syncthreads();
    }

    // write ctx [B,S,D] as fp16
    const int bb = bh >> 4;
    const int h  = bh & 15;
#pragma unroll
    for (int b = 0; b < 2; b++) {
        float inv0 = 1.0f / lacc[b][0];
        float inv1 = 1.0f / lacc[b][2];
        int s0 = q0 + wid * 32 + b * 16 + gid;
#pragma unroll
        for (int ni = 0; ni < 8; ni++) {
            int d = ni * 8 + 2 * tig;
            size_t base0 = ((size_t)bb * SS + s0) * DD + h * HDIM + d;
            size_t base1 = ((size_t)bb * SS + s0 + 8) * DD + h * HDIM + d;
            *reinterpret_cast<uint32_t*>(&g_ctxh[base0]) =
                pack_h16(oacc[b][ni][0] * inv0, oacc[b][ni][1] * inv0);
            *reinterpret_cast<uint32_t*>(&g_ctxh[base1]) =
                pack_h16(oacc[b][ni][2] * inv1, oacc[b][ni][3] * inv1);
        }
    }
}

// ---------------------------------------------------------------------------
// Kernel 4: RMS norm per row of g_x
// ---------------------------------------------------------------------------
__global__ __launch_bounds__(256) void rmsnorm_kernel(
    const float* __restrict__ scale, float* __restrict__ out)
{
    __shared__ float red[8];
    __shared__ float s_tot;
    const int row = blockIdx.x;
    const int tid = threadIdx.x;
    const float4* xr = reinterpret_cast<const float4*>(g_x + (size_t)row * DD);
    float4 xv = xr[tid];
    float ss = xv.x*xv.x + xv.y*xv.y + xv.z*xv.z + xv.w*xv.w;
#pragma unroll
    for (int off = 16; off > 0; off >>= 1)
        ss += __shfl_xor_sync(0xffffffffu, ss, off);
    if ((tid & 31) == 0) red[tid >> 5] = ss;
    __syncthreads();
    if (tid == 0) {
        float t = 0.f;
#pragma unroll
        for (int w = 0; w < 8; w++) t += red[w];
        s_tot = t;
    }
    __syncthreads();
    float rms = sqrtf(s_tot * (1.0f / DD));
    float inv = 1.0f / (rms + RMS_EPS);
    float4 sc = reinterpret_cast<const float4*>(scale)[tid];
    float4 ov;
    ov.x = xv.x * sc.x * inv;
    ov.y = xv.y * sc.y * inv;
    ov.z = xv.z * sc.z * inv;
    ov.w = xv.w * sc.w * inv;
    reinterpret_cast<float4*>(out)[(size_t)row * (DD / 4) + tid] = ov;
}

// ---------------------------------------------------------------------------
extern "C" void kernel_launch(void* const* d_in, const int* in_sizes, int n_in,
                              void* d_out, int out_size)
{
    const float* hidden = (const float*)d_in[0];
    const float* sinb   = (const float*)d_in[1];
    const float* cosb   = (const float*)d_in[2];
    const float* wq     = (const float*)d_in[3];
    const float* wk     = (const float*)d_in[4];
    const float* wv     = (const float*)d_in[5];
    const float* wo     = (const float*)d_in[6];
    const float* bo     = (const float*)d_in[7];
    const float* scale  = (const float*)d_in[8];
    float* out = (float*)d_out;

    const int n4h = MM * DD / 4;
    const int n4w = DD * DD / 4;
    cvt_h_kernel<<<(n4h + 255) / 256, 256>>>((const float4*)hidden);
    cvt_w_kernel<<<dim3((n4w + 255) / 256, 4), 256>>>(
        (const float4*)wq, (const float4*)wk, (const float4*)wv, (const float4*)wo);

    qkv_rope_mma_kernel<<<dim3(DD / 128, MM / 128, 3), 128>>>(sinb, cosb);
    attn_mma_kernel<<<dim3(SS / 128, BB * HH), 128>>>();
    oproj_mma_kernel<<<dim3(DD / 128, MM / 128), 128>>>(hidden, bo);
    rmsnorm_kernel<<<MM, 256>>>(scale, out);
}

// round 16
// speedup vs baseline: 1.4340x; 1.4340x over previous
#include <cuda_runtime.h>
#include <cuda_fp16.h>
#include <math.h>
#include <stdint.h>

// Problem constants
#define BB   2
#define SS   2048
#define DD   1024
#define HH   16
#define HDIM 64
#define MM   (BB*SS)          // 4096 rows
#define RMS_EPS 1e-8f

// Scratch (fp16 on the tensor path)
__device__ __half g_xh[MM*DD];
__device__ __half g_wqh[DD*DD];
__device__ __half g_wkh[DD*DD];
__device__ __half g_wvh[DD*DD];
__device__ __half g_woh[DD*DD];
__device__ __half g_qh[BB*HH*SS*HDIM];  // [B,H,S,HD], pre-scaled by 0.125*log2e
__device__ __half g_kh[BB*HH*SS*HDIM];
__device__ __half g_vh[BB*HH*SS*HDIM];
__device__ __half g_ctxh[MM*DD];
__device__ float g_x[MM*DD];

// ---------------------------------------------------------------------------
// helpers
// ---------------------------------------------------------------------------
__device__ __forceinline__ uint32_t smem_u32(const void* p) {
    uint32_t a;
    asm("{ .reg .u64 t; cvta.to.shared.u64 t, %1; cvt.u32.u64 %0, t; }"
        : "=r"(a) : "l"(p));
    return a;
}

__device__ __forceinline__ void mma_f16(float* d, const uint32_t* a, const uint32_t* b) {
    asm volatile(
        "mma.sync.aligned.m16n8k16.row.col.f32.f16.f16.f32 "
        "{%0,%1,%2,%3}, {%4,%5,%6,%7}, {%8,%9}, {%0,%1,%2,%3};"
        : "+f"(d[0]), "+f"(d[1]), "+f"(d[2]), "+f"(d[3])
        : "r"(a[0]), "r"(a[1]), "r"(a[2]), "r"(a[3]), "r"(b[0]), "r"(b[1]));
}

__device__ __forceinline__ void mma_f16h(uint32_t* d, const uint32_t* a, const uint32_t* b) {
    asm volatile(
        "mma.sync.aligned.m16n8k16.row.col.f16.f16.f16.f16 "
        "{%0,%1}, {%2,%3,%4,%5}, {%6,%7}, {%0,%1};"
        : "+r"(d[0]), "+r"(d[1])
        : "r"(a[0]), "r"(a[1]), "r"(a[2]), "r"(a[3]), "r"(b[0]), "r"(b[1]));
}

#define LDMX4(r0, r1, r2, r3, addr) \
    asm volatile("ldmatrix.sync.aligned.m8n8.x4.shared.b16 {%0,%1,%2,%3}, [%4];" \
                 : "=r"(r0), "=r"(r1), "=r"(r2), "=r"(r3) : "r"(addr))

#define LDMX4T(r0, r1, r2, r3, addr) \
    asm volatile("ldmatrix.sync.aligned.m8n8.x4.trans.shared.b16 {%0,%1,%2,%3}, [%4];" \
                 : "=r"(r0), "=r"(r1), "=r"(r2), "=r"(r3) : "r"(addr))

#define CP_ASYNC16(saddr, gptr) \
    asm volatile("cp.async.cg.shared.global [%0], [%1], 16;" :: "r"(saddr), "l"(gptr))
#define CP_COMMIT() asm volatile("cp.async.commit_group;")
#define CP_WAIT(N)  asm volatile("cp.async.wait_group %0;" :: "n"(N))

__device__ __forceinline__ uint32_t pack_h16(float x, float y) {
    __half2 p = __floats2half2_rn(x, y);
    return *reinterpret_cast<uint32_t*>(&p);
}

__device__ __forceinline__ uint32_t hmax2(uint32_t a, uint32_t b) {
    uint32_t r;
    asm("max.f16x2 %0, %1, %2;" : "=r"(r) : "r"(a), "r"(b));
    return r;
}
__device__ __forceinline__ uint32_t hsub2_ex2(uint32_t a, uint32_t m2) {
    uint32_t d, r;
    asm("sub.f16x2 %0, %1, %2;" : "=r"(d) : "r"(a), "r"(m2));
    asm("ex2.approx.f16x2 %0, %1;" : "=r"(r) : "r"(d));
    return r;
}
__device__ __forceinline__ float hmax_pair_to_f32(uint32_t h) {
    __half2 v = *reinterpret_cast<__half2*>(&h);
    return fmaxf(__half2float(__low2half(v)), __half2float(__high2half(v)));
}

#define ONES_H2 0x3C003C00u   // fp16 {1.0, 1.0}

// ---------------------------------------------------------------------------
// Kernel 0: fp32 -> fp16 conversion prepass
// ---------------------------------------------------------------------------
__global__ __launch_bounds__(256) void cvt_h_kernel(const float4* __restrict__ src)
{
    int i = blockIdx.x * 256 + threadIdx.x;
    if (i < MM * DD / 4) {
        float4 v = src[i];
        uint2 o;
        o.x = pack_h16(v.x, v.y);
        o.y = pack_h16(v.z, v.w);
        reinterpret_cast<uint2*>(g_xh)[i] = o;
    }
}

__global__ __launch_bounds__(256) void cvt_w_kernel(
    const float4* __restrict__ wq, const float4* __restrict__ wk,
    const float4* __restrict__ wv, const float4* __restrict__ wo)
{
    int i = blockIdx.x * 256 + threadIdx.x;
    if (i >= DD * DD / 4) return;
    int z = blockIdx.y;
    const float4* s = (z == 0) ? wq : (z == 1) ? wk : (z == 2) ? wv : wo;
    __half* dp = (z == 0) ? g_wqh : (z == 1) ? g_wkh : (z == 2) ? g_wvh : g_woh;
    float4 v = s[i];
    uint2 o;
    o.x = pack_h16(v.x, v.y);
    o.y = pack_h16(v.z, v.w);
    reinterpret_cast<uint2*>(dp)[i] = o;
}

// ---------------------------------------------------------------------------
// fp16 GEMM mainloop: 128x128 tile, 4 warps, warp tile 64x64.
// 3-stage cp.async ring, ONE __syncthreads per k-iteration.
// Dynamic smem: As[3*TILEB] then Bs[3*TILEB]  (61440 bytes total)
// ---------------------------------------------------------------------------
#define KCB   32
#define SAB   40
#define TILEB (128 * SAB)
#define NKIT  (DD / KCB)                 // 32
#define GEMM_SMEM_B (6 * TILEB * 2)      // 61440

__device__ __forceinline__ void gemm_mainloop_f16(
    float (&acc)[4][8][4],
    const __half* __restrict__ A, const __half* __restrict__ W,
    int m0, int n0, __half* As, __half* Bs)
{
    const int tid  = threadIdx.x;
    const int wid  = tid >> 5, lane = tid & 31;
    const int wm = wid & 1, wn = wid >> 1;

    const uint32_t as_base = smem_u32(As);
    const uint32_t bs_base = smem_u32(Bs);

    uint32_t a_off[4], b_off[4];
#pragma unroll
    for (int mi = 0; mi < 4; mi++)
        a_off[mi] = (uint32_t)(((wm * 64 + mi * 16 + (lane & 15)) * SAB + (lane >> 4) * 8) * 2);
#pragma unroll
    for (int nip = 0; nip < 4; nip++)
        b_off[nip] = (uint32_t)(((wn * 64 + nip * 16 + (lane & 7) + ((lane >> 4) & 1) * 8) * SAB
                                 + ((lane >> 3) & 1) * 8) * 2);

#pragma unroll
    for (int mi = 0; mi < 4; mi++)
#pragma unroll
        for (int ni = 0; ni < 8; ni++)
#pragma unroll
            for (int c = 0; c < 4; c++) acc[mi][ni][c] = 0.f;

    auto issue = [&](int buf, int k0) {
#pragma unroll
        for (int r = 0; r < 4; r++) {
            int idx = tid + (r << 7);
            int row = idx >> 2, c = idx & 3;
            uint32_t soff = (uint32_t)((buf * TILEB + row * SAB) * 2 + c * 16);
            const char* ga = (const char*)(A + (size_t)(m0 + row) * DD + k0) + c * 16;
            const char* gb = (const char*)(W + (size_t)(n0 + row) * DD + k0) + c * 16;
            CP_ASYNC16(as_base + soff, ga);
            CP_ASYNC16(bs_base + soff, gb);
        }
        CP_COMMIT();
    };

    issue(0, 0);
    issue(1, KCB);
    for (int it = 0; it < NKIT; it++) {
        int buf = it % 3;
        if (it < NKIT - 1) { CP_WAIT(1); } else { CP_WAIT(0); }
        __syncthreads();
        if (it + 2 < NKIT) issue((it + 2) % 3, (it + 2) * KCB);

        uint32_t abase = as_base + (uint32_t)(buf * TILEB * 2);
        uint32_t bbase = bs_base + (uint32_t)(buf * TILEB * 2);
#pragma unroll
        for (int ks = 0; ks < KCB; ks += 16) {
            uint32_t af[4][4], bf[8][2];
#pragma unroll
            for (int mi = 0; mi < 4; mi++)
                LDMX4(af[mi][0], af[mi][1], af[mi][2], af[mi][3],
                      abase + a_off[mi] + ks * 2);
#pragma unroll
            for (int nip = 0; nip < 4; nip++)
                LDMX4(bf[2 * nip][0], bf[2 * nip][1], bf[2 * nip + 1][0], bf[2 * nip + 1][1],
                      bbase + b_off[nip] + ks * 2);
#pragma unroll
            for (int mi = 0; mi < 4; mi++)
#pragma unroll
                for (int ni = 0; ni < 8; ni++)
                    mma_f16(acc[mi][ni], af[mi], bf[ni]);
        }
    }
    __syncthreads();
}

// ---------------------------------------------------------------------------
// Kernel 1: QKV projection + RoPE + scatter to [B,H,S,HD]
// ---------------------------------------------------------------------------
__global__ __launch_bounds__(128) void qkv_rope_mma_kernel(
    const float* __restrict__ sinb, const float* __restrict__ cosb)
{
    extern __shared__ __half gsm[];
    __half* As = gsm;
    __half* Bs = gsm + 3 * TILEB;

    const int m0 = blockIdx.y << 7;
    const int n0 = blockIdx.x << 7;
    const int z  = blockIdx.z;
    const __half* W = (z == 0) ? g_wqh : (z == 1 ? g_wkh : g_wvh);
    __half* outp    = (z == 0) ? g_qh  : (z == 1 ? g_kh  : g_vh);

    float acc[4][8][4];
    gemm_mainloop_f16(acc, g_xh, W, m0, n0, As, Bs);

    const int tid = threadIdx.x, wid = tid >> 5, lane = tid & 31;
    const int wm = wid & 1, wn = wid >> 1;
    const int gid = lane >> 2, tig = lane & 3;
    const float qs = (z == 0) ? 0.125f * 1.44269504088896f : 1.0f;

#pragma unroll
    for (int mi = 0; mi < 4; mi++) {
#pragma unroll
        for (int half = 0; half < 2; half++) {
            int m  = m0 + wm * 64 + mi * 16 + gid + half * 8;
            int bb = m >> 11;
            int s  = m & (SS - 1);
#pragma unroll
            for (int ni = 0; ni < 8; ni++) {
                int n  = n0 + wn * 64 + ni * 8 + 2 * tig;
                int h  = n >> 6;
                int hd = n & 63;
                int ir = hd >> 1;
                float sn = sinb[s * (HDIM / 2) + ir];
                float cs = cosb[s * (HDIM / 2) + ir];
                float x1 = acc[mi][ni][half * 2 + 0];
                float x2 = acc[mi][ni][half * 2 + 1];
                float o1 = (x1 * cs - x2 * sn) * qs;
                float o2 = (x2 * cs + x1 * sn) * qs;
                size_t base = ((size_t)(bb * HH + h) * SS + s) * HDIM + hd;
                *reinterpret_cast<uint32_t*>(&outp[base]) = pack_h16(o1, o2);
            }
        }
    }
}

// ---------------------------------------------------------------------------
// Kernel 3: O-proj + bias + residual -> g_x (fp32)
// ---------------------------------------------------------------------------
__global__ __launch_bounds__(128) void oproj_mma_kernel(
    const float* __restrict__ hidden, const float* __restrict__ bo)
{
    extern __shared__ __half gsm[];
    __half* As = gsm;
    __half* Bs = gsm + 3 * TILEB;

    const int m0 = blockIdx.y << 7;
    const int n0 = blockIdx.x << 7;

    float acc[4][8][4];
    gemm_mainloop_f16(acc, g_ctxh, g_woh, m0, n0, As, Bs);

    const int tid = threadIdx.x, wid = tid >> 5, lane = tid & 31;
    const int wm = wid & 1, wn = wid >> 1;
    const int gid = lane >> 2, tig = lane & 3;

#pragma unroll
    for (int mi = 0; mi < 4; mi++) {
#pragma unroll
        for (int half = 0; half < 2; half++) {
            int m = m0 + wm * 64 + mi * 16 + gid + half * 8;
#pragma unroll
            for (int ni = 0; ni < 8; ni++) {
                int n = n0 + wn * 64 + ni * 8 + 2 * tig;
                float2 hv = *reinterpret_cast<const float2*>(&hidden[(size_t)m * DD + n]);
                float2 bv = *reinterpret_cast<const float2*>(&bo[n]);
                float2 o;
                o.x = acc[mi][ni][half * 2 + 0] + bv.x + hv.x;
                o.y = acc[mi][ni][half * 2 + 1] + bv.y + hv.y;
                *reinterpret_cast<float2*>(&g_x[(size_t)m * DD + n]) = o;
            }
        }
    }
}

// ---------------------------------------------------------------------------
// Kernel 2: flash attention — QK^T fp16 accum, f16x2 softmax, PV fp32 accum.
// 3-stage cp.async ring for K/V, ONE __syncthreads per tile.
// Dynamic smem: Ks[3*AT_TILE] then Vs[3*AT_TILE]  (55296 bytes)
// ---------------------------------------------------------------------------
#define KSTRB 72
#define AT_TILE (64 * KSTRB)
#define NTIL (SS / 64)                   // 32
#define ATTN_SMEM_B (6 * AT_TILE * 2)    // 55296

__global__ __launch_bounds__(128) void attn_mma_kernel()
{
    extern __shared__ __half asm_[];
    __half* Ks = asm_;
    __half* Vs = asm_ + 3 * AT_TILE;

    const int tid = threadIdx.x, wid = tid >> 5, lane = tid & 31;
    const int gid = lane >> 2, tig = lane & 3;
    const int q0 = blockIdx.x << 7;
    const int bh = blockIdx.y;
    const __half* qp = g_qh + (size_t)bh * SS * HDIM;
    const __half* kp = g_kh + (size_t)bh * SS * HDIM;
    const __half* vp = g_vh + (size_t)bh * SS * HDIM;

    const uint32_t ks_base = smem_u32(Ks);
    const uint32_t vs_base = smem_u32(Vs);

    uint32_t ap_off[2];
#pragma unroll
    for (int b = 0; b < 2; b++)
        ap_off[b] = (uint32_t)(((wid * 32 + b * 16 + (lane & 15)) * KSTRB + (lane >> 4) * 8) * 2);
    const uint32_t kb_off = (uint32_t)((((lane & 7) + ((lane >> 4) & 1) * 8) * KSTRB
                                        + ((lane >> 3) & 1) * 8) * 2);
    const uint32_t vt_off = (uint32_t)(((lane & 15) * KSTRB + ((lane >> 4) & 1) * 8) * 2);

    // stage Q tile through Ks rows 0..127, grab frags
#pragma unroll
    for (int r = 0; r < 8; r++) {
        int idx = tid + (r << 7);
        int row = idx >> 3, c = idx & 7;
        *reinterpret_cast<uint4*>(&Ks[row * KSTRB + c * 8]) =
            *reinterpret_cast<const uint4*>(&qp[(size_t)(q0 + row) * HDIM + c * 8]);
    }
    __syncthreads();

    uint32_t qf[2][4][4];
#pragma unroll
    for (int b = 0; b < 2; b++)
#pragma unroll
        for (int kk = 0; kk < 4; kk++)
            LDMX4(qf[b][kk][0], qf[b][kk][1], qf[b][kk][2], qf[b][kk][3],
                  ks_base + ap_off[b] + kk * 32);
    __syncthreads();

    float oacc[2][8][4];
#pragma unroll
    for (int b = 0; b < 2; b++)
#pragma unroll
        for (int ni = 0; ni < 8; ni++)
#pragma unroll
            for (int c = 0; c < 4; c++) oacc[b][ni][c] = 0.f;
    float mrow[2][2] = {{-1e30f, -1e30f}, {-1e30f, -1e30f}};
    float lacc[2][4] = {{0.f, 0.f, 0.f, 0.f}, {0.f, 0.f, 0.f, 0.f}};
    const uint32_t onesb[2] = {ONES_H2, ONES_H2};

    auto issue = [&](int buf, int kt) {
#pragma unroll
        for (int r = 0; r < 4; r++) {
            int c = tid + (r << 7);
            int row = c >> 3, col = (c & 7) * 8;
            uint32_t so = (uint32_t)(((buf * 64 + row) * KSTRB + col) * 2);
            CP_ASYNC16(ks_base + so, kp + (size_t)(kt + row) * HDIM + col);
            CP_ASYNC16(vs_base + so, vp + (size_t)(kt + row) * HDIM + col);
        }
        CP_COMMIT();
    };

    issue(0, 0);
    issue(1, 64);
    for (int t = 0; t < NTIL; t++) {
        int buf = t % 3;
        if (t < NTIL - 1) { CP_WAIT(1); } else { CP_WAIT(0); }
        __syncthreads();
        if (t + 2 < NTIL) issue((t + 2) % 3, (t + 2) * 64);

        uint32_t kb = ks_base + (uint32_t)(buf * AT_TILE * 2);
        uint32_t vb = vs_base + (uint32_t)(buf * AT_TILE * 2);

        // S = Q K^T (fp16 accum, packed)
        uint32_t sacc[2][8][2];
#pragma unroll
        for (int b = 0; b < 2; b++)
#pragma unroll
            for (int ni = 0; ni < 8; ni++) {
                sacc[b][ni][0] = 0u; sacc[b][ni][1] = 0u;
            }

#pragma unroll
        for (int kk = 0; kk < 4; kk++) {
            uint32_t kf[8][2];
#pragma unroll
            for (int nip = 0; nip < 4; nip++)
                LDMX4(kf[2 * nip][0], kf[2 * nip][1], kf[2 * nip + 1][0], kf[2 * nip + 1][1],
                      kb + kb_off + (uint32_t)(nip * 16 * KSTRB * 2) + kk * 32);
#pragma unroll
            for (int ni = 0; ni < 8; ni++) {
                mma_f16h(sacc[0][ni], qf[0][kk], kf[ni]);
                mma_f16h(sacc[1][ni], qf[1][kk], kf[ni]);
            }
        }

        // softmax in f16x2
#pragma unroll
        for (int b = 0; b < 2; b++) {
            uint32_t pm0 = sacc[b][0][0], pm1 = sacc[b][0][1];
#pragma unroll
            for (int ni = 1; ni < 8; ni++) {
                pm0 = hmax2(pm0, sacc[b][ni][0]);
                pm1 = hmax2(pm1, sacc[b][ni][1]);
            }
            float mx0 = hmax_pair_to_f32(pm0);
            float mx1 = hmax_pair_to_f32(pm1);
#pragma unroll
            for (int off = 1; off <= 2; off <<= 1) {
                mx0 = fmaxf(mx0, __shfl_xor_sync(0xffffffffu, mx0, off));
                mx1 = fmaxf(mx1, __shfl_xor_sync(0xffffffffu, mx1, off));
            }
            float mn0 = fmaxf(mrow[b][0], mx0), mn1 = fmaxf(mrow[b][1], mx1);
            float corr0 = exp2f(mrow[b][0] - mn0), corr1 = exp2f(mrow[b][1] - mn1);
            mrow[b][0] = mn0; mrow[b][1] = mn1;
            uint32_t m20 = pack_h16(mn0, mn0);
            uint32_t m21 = pack_h16(mn1, mn1);
#pragma unroll
            for (int ni = 0; ni < 8; ni++) {
                sacc[b][ni][0] = hsub2_ex2(sacc[b][ni][0], m20);
                sacc[b][ni][1] = hsub2_ex2(sacc[b][ni][1], m21);
            }
            lacc[b][0] *= corr0; lacc[b][1] *= corr0;
            lacc[b][2] *= corr1; lacc[b][3] *= corr1;
#pragma unroll
            for (int ni = 0; ni < 8; ni++) {
                oacc[b][ni][0] *= corr0; oacc[b][ni][1] *= corr0;
                oacc[b][ni][2] *= corr1; oacc[b][ni][3] *= corr1;
            }
        }

        // O += P V; l += P @ 1
#pragma unroll
        for (int kk = 0; kk < 4; kk++) {
            uint32_t vf[8][2];
#pragma unroll
            for (int nip = 0; nip < 4; nip++)
                LDMX4T(vf[2 * nip][0], vf[2 * nip][1], vf[2 * nip + 1][0], vf[2 * nip + 1][1],
                       vb + vt_off + (uint32_t)((kk * 16 * KSTRB + nip * 16) * 2));
#pragma unroll
            for (int b = 0; b < 2; b++) {
                uint32_t pf[4];
                pf[0] = sacc[b][2 * kk][0];
                pf[1] = sacc[b][2 * kk][1];
                pf[2] = sacc[b][2 * kk + 1][0];
                pf[3] = sacc[b][2 * kk + 1][1];
#pragma unroll
                for (int ni = 0; ni < 8; ni++)
                    mma_f16(oacc[b][ni], pf, vf[ni]);
                mma_f16(lacc[b], pf, onesb);
            }
        }
    }

    // write ctx [B,S,D] as fp16
    const int bb = bh >> 4;
    const int h  = bh & 15;
#pragma unroll
    for (int b = 0; b < 2; b++) {
        float inv0 = 1.0f / lacc[b][0];
        float inv1 = 1.0f / lacc[b][2];
        int s0 = q0 + wid * 32 + b * 16 + gid;
#pragma unroll
        for (int ni = 0; ni < 8; ni++) {
            int d = ni * 8 + 2 * tig;
            size_t base0 = ((size_t)bb * SS + s0) * DD + h * HDIM + d;
            size_t base1 = ((size_t)bb * SS + s0 + 8) * DD + h * HDIM + d;
            *reinterpret_cast<uint32_t*>(&g_ctxh[base0]) =
                pack_h16(oacc[b][ni][0] * inv0, oacc[b][ni][1] * inv0);
            *reinterpret_cast<uint32_t*>(&g_ctxh[base1]) =
                pack_h16(oacc[b][ni][2] * inv1, oacc[b][ni][3] * inv1);
        }
    }
}

// ---------------------------------------------------------------------------
// Kernel 4: RMS norm per row of g_x
// ---------------------------------------------------------------------------
__global__ __launch_bounds__(256) void rmsnorm_kernel(
    const float* __restrict__ scale, float* __restrict__ out)
{
    __shared__ float red[8];
    __shared__ float s_tot;
    const int row = blockIdx.x;
    const int tid = threadIdx.x;
    const float4* xr = reinterpret_cast<const float4*>(g_x + (size_t)row * DD);
    float4 xv = xr[tid];
    float ss = xv.x*xv.x + xv.y*xv.y + xv.z*xv.z + xv.w*xv.w;
#pragma unroll
    for (int off = 16; off > 0; off >>= 1)
        ss += __shfl_xor_sync(0xffffffffu, ss, off);
    if ((tid & 31) == 0) red[tid >> 5] = ss;
    __syncthreads();
    if (tid == 0) {
        float t = 0.f;
#pragma unroll
        for (int w = 0; w < 8; w++) t += red[w];
        s_tot = t;
    }
    __syncthreads();
    float rms = sqrtf(s_tot * (1.0f / DD));
    float inv = 1.0f / (rms + RMS_EPS);
    float4 sc = reinterpret_cast<const float4*>(scale)[tid];
    float4 ov;
    ov.x = xv.x * sc.x * inv;
    ov.y = xv.y * sc.y * inv;
    ov.z = xv.z * sc.z * inv;
    ov.w = xv.w * sc.w * inv;
    reinterpret_cast<float4*>(out)[(size_t)row * (DD / 4) + tid] = ov;
}

// ---------------------------------------------------------------------------
extern "C" void kernel_launch(void* const* d_in, const int* in_sizes, int n_in,
                              void* d_out, int out_size)
{
    const float* hidden = (const float*)d_in[0];
    const float* sinb   = (const float*)d_in[1];
    const float* cosb   = (const float*)d_in[2];
    const float* wq     = (const float*)d_in[3];
    const float* wk     = (const float*)d_in[4];
    const float* wv     = (const float*)d_in[5];
    const float* wo     = (const float*)d_in[6];
    const float* bo     = (const float*)d_in[7];
    const float* scale  = (const float*)d_in[8];
    float* out = (float*)d_out;

    static bool attr_done = false;
    if (!attr_done) {
        cudaFuncSetAttribute(qkv_rope_mma_kernel,
                             cudaFuncAttributeMaxDynamicSharedMemorySize, GEMM_SMEM_B);
        cudaFuncSetAttribute(oproj_mma_kernel,
                             cudaFuncAttributeMaxDynamicSharedMemorySize, GEMM_SMEM_B);
        cudaFuncSetAttribute(attn_mma_kernel,
                             cudaFuncAttributeMaxDynamicSharedMemorySize, ATTN_SMEM_B);
        attr_done = true;
    }

    const int n4h = MM * DD / 4;
    const int n4w = DD * DD / 4;
    cvt_h_kernel<<<(n4h + 255) / 256, 256>>>((const float4*)hidden);
    cvt_w_kernel<<<dim3((n4w + 255) / 256, 4), 256>>>(
        (const float4*)wq, (const float4*)wk, (const float4*)wv, (const float4*)wo);

    qkv_rope_mma_kernel<<<dim3(DD / 128, MM / 128, 3), 128, GEMM_SMEM_B>>>(sinb, cosb);
    attn_mma_kernel<<<dim3(SS / 128, BB * HH), 128, ATTN_SMEM_B>>>();
    oproj_mma_kernel<<<dim3(DD / 128, MM / 128), 128, GEMM_SMEM_B>>>(hidden, bo);
    rmsnorm_kernel<<<MM, 256>>>(scale, out);
}

// round 17
// speedup vs baseline: 1.5275x; 1.0652x over previous
#include <cuda_runtime.h>
#include <cuda_fp16.h>
#include <math.h>
#include <stdint.h>

// Problem constants
#define BB   2
#define SS   2048
#define DD   1024
#define HH   16
#define HDIM 64
#define MM   (BB*SS)          // 4096 rows
#define RMS_EPS 1e-8f

// Scratch (fp16 on the tensor path)
__device__ __half g_xh[MM*DD];          // hidden in fp16
__device__ __half g_wqh[DD*DD];
__device__ __half g_wkh[DD*DD];
__device__ __half g_wvh[DD*DD];
__device__ __half g_woh[DD*DD];
__device__ __half g_qh[BB*HH*SS*HDIM];  // [B,H,S,HD], pre-scaled by 0.125*log2e
__device__ __half g_kh[BB*HH*SS*HDIM];  // [B,H,S,HD]
__device__ __half g_vh[BB*HH*SS*HDIM];  // [B,H,S,HD]
__device__ __half g_ctxh[MM*DD];        // [B,S,D]
__device__ float g_x[MM*DD];            // post-proj + residual (fp32)

// ---------------------------------------------------------------------------
// helpers
// ---------------------------------------------------------------------------
__device__ __forceinline__ uint32_t smem_u32(const void* p) {
    uint32_t a;
    asm("{ .reg .u64 t; cvta.to.shared.u64 t, %1; cvt.u32.u64 %0, t; }"
        : "=r"(a) : "l"(p));
    return a;
}

// D += A(16x16) * B(16x8), fp16 inputs, fp32 accum
__device__ __forceinline__ void mma_f16(float* d, const uint32_t* a, const uint32_t* b) {
    asm volatile(
        "mma.sync.aligned.m16n8k16.row.col.f32.f16.f16.f32 "
        "{%0,%1,%2,%3}, {%4,%5,%6,%7}, {%8,%9}, {%0,%1,%2,%3};"
        : "+f"(d[0]), "+f"(d[1]), "+f"(d[2]), "+f"(d[3])
        : "r"(a[0]), "r"(a[1]), "r"(a[2]), "r"(a[3]), "r"(b[0]), "r"(b[1]));
}

#define LDMX4(r0, r1, r2, r3, addr) \
    asm volatile("ldmatrix.sync.aligned.m8n8.x4.shared.b16 {%0,%1,%2,%3}, [%4];" \
                 : "=r"(r0), "=r"(r1), "=r"(r2), "=r"(r3) : "r"(addr))

#define LDMX4T(r0, r1, r2, r3, addr) \
    asm volatile("ldmatrix.sync.aligned.m8n8.x4.trans.shared.b16 {%0,%1,%2,%3}, [%4];" \
                 : "=r"(r0), "=r"(r1), "=r"(r2), "=r"(r3) : "r"(addr))

#define CP_ASYNC16(saddr, gptr) \
    asm volatile("cp.async.cg.shared.global [%0], [%1], 16;" :: "r"(saddr), "l"(gptr))
#define CP_COMMIT() asm volatile("cp.async.commit_group;")
#define CP_WAIT(N)  asm volatile("cp.async.wait_group %0;" :: "n"(N))

__device__ __forceinline__ uint32_t pack_h16(float x, float y) {
    __half2 p = __floats2half2_rn(x, y);
    return *reinterpret_cast<uint32_t*>(&p);
}

// exp2 of two fp32 values -> packed fp16x2 (one MUFU for both)
__device__ __forceinline__ uint32_t exp2_h2(float lo, float hi) {
    uint32_t h, r;
    asm("cvt.rn.f16x2.f32 %0, %1, %2;" : "=r"(h) : "f"(hi), "f"(lo));
    asm("ex2.approx.f16x2 %0, %1;" : "=r"(r) : "r"(h));
    return r;
}

#define ONES_H2 0x3C003C00u   // fp16 {1.0, 1.0}

// ---------------------------------------------------------------------------
// Kernel 0: fp32 -> fp16 conversion prepass
// ---------------------------------------------------------------------------
__global__ __launch_bounds__(256) void cvt_h_kernel(const float4* __restrict__ src)
{
    int i = blockIdx.x * 256 + threadIdx.x;
    if (i < MM * DD / 4) {
        float4 v = src[i];
        uint2 o;
        o.x = pack_h16(v.x, v.y);
        o.y = pack_h16(v.z, v.w);
        reinterpret_cast<uint2*>(g_xh)[i] = o;
    }
}

__global__ __launch_bounds__(256) void cvt_w_kernel(
    const float4* __restrict__ wq, const float4* __restrict__ wk,
    const float4* __restrict__ wv, const float4* __restrict__ wo)
{
    int i = blockIdx.x * 256 + threadIdx.x;
    if (i >= DD * DD / 4) return;
    int z = blockIdx.y;
    const float4* s = (z == 0) ? wq : (z == 1) ? wk : (z == 2) ? wv : wo;
    __half* dp = (z == 0) ? g_wqh : (z == 1) ? g_wkh : (z == 2) ? g_wvh : g_woh;
    float4 v = s[i];
    uint2 o;
    o.x = pack_h16(v.x, v.y);
    o.y = pack_h16(v.z, v.w);
    reinterpret_cast<uint2*>(dp)[i] = o;
}

// ---------------------------------------------------------------------------
// fp16 GEMM mainloop: 128x128 tile, 4 warps, warp tile 64x64.
// 2-stage cp.async, ONE __syncthreads per k-iter (wait -> sync -> issue).
// ---------------------------------------------------------------------------
#define KCB   32
#define SAB   40
#define TILEB (128 * SAB)

__device__ __forceinline__ void gemm_mainloop_f16(
    float (&acc)[4][8][4],
    const __half* __restrict__ A, const __half* __restrict__ W,
    int m0, int n0, __half* As, __half* Bs)
{
    const int tid  = threadIdx.x;
    const int wid  = tid >> 5, lane = tid & 31;
    const int wm = wid & 1, wn = wid >> 1;

    const uint32_t as_base = smem_u32(As);
    const uint32_t bs_base = smem_u32(Bs);

    uint32_t a_off[4], b_off[4];
#pragma unroll
    for (int mi = 0; mi < 4; mi++)
        a_off[mi] = (uint32_t)(((wm * 64 + mi * 16 + (lane & 15)) * SAB + (lane >> 4) * 8) * 2);
#pragma unroll
    for (int nip = 0; nip < 4; nip++)
        b_off[nip] = (uint32_t)(((wn * 64 + nip * 16 + (lane & 7) + ((lane >> 4) & 1) * 8) * SAB
                                 + ((lane >> 3) & 1) * 8) * 2);

#pragma unroll
    for (int mi = 0; mi < 4; mi++)
#pragma unroll
        for (int ni = 0; ni < 8; ni++)
#pragma unroll
            for (int c = 0; c < 4; c++) acc[mi][ni][c] = 0.f;

    auto issue = [&](int buf, int k0) {
#pragma unroll
        for (int r = 0; r < 4; r++) {
            int idx = tid + (r << 7);
            int row = idx >> 2, c = idx & 3;
            uint32_t soff = (uint32_t)((buf * TILEB + row * SAB) * 2 + c * 16);
            const char* ga = (const char*)(A + (size_t)(m0 + row) * DD + k0) + c * 16;
            const char* gb = (const char*)(W + (size_t)(n0 + row) * DD + k0) + c * 16;
            CP_ASYNC16(as_base + soff, ga);
            CP_ASYNC16(bs_base + soff, gb);
        }
        CP_COMMIT();
    };

    issue(0, 0);
    for (int k0 = 0; k0 < DD; k0 += KCB) {
        int buf = (k0 / KCB) & 1;
        CP_WAIT(0);
        __syncthreads();
        if (k0 + KCB < DD) issue(buf ^ 1, k0 + KCB);

        uint32_t abase = as_base + (uint32_t)(buf * TILEB * 2);
        uint32_t bbase = bs_base + (uint32_t)(buf * TILEB * 2);
#pragma unroll
        for (int ks = 0; ks < KCB; ks += 16) {
            uint32_t af[4][4], bf[8][2];
#pragma unroll
            for (int mi = 0; mi < 4; mi++)
                LDMX4(af[mi][0], af[mi][1], af[mi][2], af[mi][3],
                      abase + a_off[mi] + ks * 2);
#pragma unroll
            for (int nip = 0; nip < 4; nip++)
                LDMX4(bf[2 * nip][0], bf[2 * nip][1], bf[2 * nip + 1][0], bf[2 * nip + 1][1],
                      bbase + b_off[nip] + ks * 2);
#pragma unroll
            for (int mi = 0; mi < 4; mi++)
#pragma unroll
                for (int ni = 0; ni < 8; ni++)
                    mma_f16(acc[mi][ni], af[mi], bf[ni]);
        }
    }
}

// ---------------------------------------------------------------------------
// Kernel 1: QKV projection + RoPE + scatter to [B,H,S,HD]
// ---------------------------------------------------------------------------
__global__ __launch_bounds__(128) void qkv_rope_mma_kernel(
    const float* __restrict__ sinb, const float* __restrict__ cosb)
{
    __shared__ __half As[2 * TILEB];
    __shared__ __half Bs[2 * TILEB];

    const int m0 = blockIdx.y << 7;
    const int n0 = blockIdx.x << 7;
    const int z  = blockIdx.z;
    const __half* W = (z == 0) ? g_wqh : (z == 1 ? g_wkh : g_wvh);
    __half* outp    = (z == 0) ? g_qh  : (z == 1 ? g_kh  : g_vh);

    float acc[4][8][4];
    gemm_mainloop_f16(acc, g_xh, W, m0, n0, As, Bs);

    const int tid = threadIdx.x, wid = tid >> 5, lane = tid & 31;
    const int wm = wid & 1, wn = wid >> 1;
    const int gid = lane >> 2, tig = lane & 3;
    const float qs = (z == 0) ? 0.125f * 1.44269504088896f : 1.0f;

#pragma unroll
    for (int mi = 0; mi < 4; mi++) {
#pragma unroll
        for (int half = 0; half < 2; half++) {
            int m  = m0 + wm * 64 + mi * 16 + gid + half * 8;
            int bb = m >> 11;
            int s  = m & (SS - 1);
#pragma unroll
            for (int ni = 0; ni < 8; ni++) {
                int n  = n0 + wn * 64 + ni * 8 + 2 * tig;
                int h  = n >> 6;
                int hd = n & 63;
                int ir = hd >> 1;
                float sn = sinb[s * (HDIM / 2) + ir];
                float cs = cosb[s * (HDIM / 2) + ir];
                float x1 = acc[mi][ni][half * 2 + 0];
                float x2 = acc[mi][ni][half * 2 + 1];
                float o1 = (x1 * cs - x2 * sn) * qs;
                float o2 = (x2 * cs + x1 * sn) * qs;
                size_t base = ((size_t)(bb * HH + h) * SS + s) * HDIM + hd;
                *reinterpret_cast<uint32_t*>(&outp[base]) = pack_h16(o1, o2);
            }
        }
    }
}

// ---------------------------------------------------------------------------
// Kernel 3: O-proj + bias + residual -> g_x (fp32)
// ---------------------------------------------------------------------------
__global__ __launch_bounds__(128) void oproj_mma_kernel(
    const float* __restrict__ hidden, const float* __restrict__ bo)
{
    __shared__ __half As[2 * TILEB];
    __shared__ __half Bs[2 * TILEB];

    const int m0 = blockIdx.y << 7;
    const int n0 = blockIdx.x << 7;

    float acc[4][8][4];
    gemm_mainloop_f16(acc, g_ctxh, g_woh, m0, n0, As, Bs);

    const int tid = threadIdx.x, wid = tid >> 5, lane = tid & 31;
    const int wm = wid & 1, wn = wid >> 1;
    const int gid = lane >> 2, tig = lane & 3;

#pragma unroll
    for (int mi = 0; mi < 4; mi++) {
#pragma unroll
        for (int half = 0; half < 2; half++) {
            int m = m0 + wm * 64 + mi * 16 + gid + half * 8;
#pragma unroll
            for (int ni = 0; ni < 8; ni++) {
                int n = n0 + wn * 64 + ni * 8 + 2 * tig;
                float2 hv = *reinterpret_cast<const float2*>(&hidden[(size_t)m * DD + n]);
                float2 bv = *reinterpret_cast<const float2*>(&bo[n]);
                float2 o;
                o.x = acc[mi][ni][half * 2 + 0] + bv.x + hv.x;
                o.y = acc[mi][ni][half * 2 + 1] + bv.y + hv.y;
                *reinterpret_cast<float2*>(&g_x[(size_t)m * DD + n]) = o;
            }
        }
    }
}

// ---------------------------------------------------------------------------
// Kernel 2: flash attention — fp16, log2-domain softmax, f16x2 ex2,
// row-sum via ones-MMA, V via trans-ldmatrix. 4 warps x 32 q rows.
// 2-stage cp.async, ONE sync per tile (wait -> sync -> issue), race-free.
// ---------------------------------------------------------------------------
#define KSTRB 72
#define AT_TILE (64 * KSTRB)

__global__ __launch_bounds__(128) void attn_mma_kernel()
{
    __shared__ __half Ks[2 * AT_TILE];
    __shared__ __half Vs[2 * AT_TILE];

    const int tid = threadIdx.x, wid = tid >> 5, lane = tid & 31;
    const int gid = lane >> 2, tig = lane & 3;
    const int q0 = blockIdx.x << 7;
    const int bh = blockIdx.y;
    const __half* qp = g_qh + (size_t)bh * SS * HDIM;
    const __half* kp = g_kh + (size_t)bh * SS * HDIM;
    const __half* vp = g_vh + (size_t)bh * SS * HDIM;

    const uint32_t ks_base = smem_u32(Ks);
    const uint32_t vs_base = smem_u32(Vs);

    uint32_t ap_off[2];
#pragma unroll
    for (int b = 0; b < 2; b++)
        ap_off[b] = (uint32_t)(((wid * 32 + b * 16 + (lane & 15)) * KSTRB + (lane >> 4) * 8) * 2);
    const uint32_t kb_off = (uint32_t)((((lane & 7) + ((lane >> 4) & 1) * 8) * KSTRB
                                        + ((lane >> 3) & 1) * 8) * 2);
    const uint32_t vt_off = (uint32_t)(((lane & 15) * KSTRB + ((lane >> 4) & 1) * 8) * 2);

    // stage Q tile [128][64] through Ks, grab frags
#pragma unroll
    for (int r = 0; r < 8; r++) {
        int idx = tid + (r << 7);
        int row = idx >> 3, c = idx & 7;
        *reinterpret_cast<uint4*>(&Ks[row * KSTRB + c * 8]) =
            *reinterpret_cast<const uint4*>(&qp[(size_t)(q0 + row) * HDIM + c * 8]);
    }
    __syncthreads();

    uint32_t qf[2][4][4];
#pragma unroll
    for (int b = 0; b < 2; b++)
#pragma unroll
        for (int kk = 0; kk < 4; kk++)
            LDMX4(qf[b][kk][0], qf[b][kk][1], qf[b][kk][2], qf[b][kk][3],
                  ks_base + ap_off[b] + kk * 32);
    __syncthreads();

    float oacc[2][8][4];
#pragma unroll
    for (int b = 0; b < 2; b++)
#pragma unroll
        for (int ni = 0; ni < 8; ni++)
#pragma unroll
            for (int c = 0; c < 4; c++) oacc[b][ni][c] = 0.f;
    float mrow[2][2] = {{-1e30f, -1e30f}, {-1e30f, -1e30f}};
    float lacc[2][4] = {{0.f, 0.f, 0.f, 0.f}, {0.f, 0.f, 0.f, 0.f}};
    const uint32_t onesb[2] = {ONES_H2, ONES_H2};

    auto issue = [&](int buf, int kt) {
#pragma unroll
        for (int r = 0; r < 4; r++) {
            int c = tid + (r << 7);
            int row = c >> 3, col = (c & 7) * 8;
            uint32_t so = (uint32_t)(((buf * 64 + row) * KSTRB + col) * 2);
            CP_ASYNC16(ks_base + so, kp + (size_t)(kt + row) * HDIM + col);
            CP_ASYNC16(vs_base + so, vp + (size_t)(kt + row) * HDIM + col);
        }
        CP_COMMIT();
    };

    issue(0, 0);
    for (int t = 0; t < SS / 64; t++) {
        int buf = t & 1;
        CP_WAIT(0);
        __syncthreads();
        if (t + 1 < SS / 64) issue(buf ^ 1, (t + 1) * 64);

        uint32_t kb = ks_base + (uint32_t)(buf * AT_TILE * 2);
        uint32_t vb = vs_base + (uint32_t)(buf * AT_TILE * 2);

        // S = Q K^T (log2-domain: q pre-scaled by 0.125*log2e)
        float sacc[2][8][4];
#pragma unroll
        for (int b = 0; b < 2; b++)
#pragma unroll
            for (int ni = 0; ni < 8; ni++)
#pragma unroll
                for (int c = 0; c < 4; c++) sacc[b][ni][c] = 0.f;

#pragma unroll
        for (int kk = 0; kk < 4; kk++) {
            uint32_t kf[8][2];
#pragma unroll
            for (int nip = 0; nip < 4; nip++)
                LDMX4(kf[2 * nip][0], kf[2 * nip][1], kf[2 * nip + 1][0], kf[2 * nip + 1][1],
                      kb + kb_off + (uint32_t)(nip * 16 * KSTRB * 2) + kk * 32);
#pragma unroll
            for (int ni = 0; ni < 8; ni++) {
                mma_f16(sacc[0][ni], qf[0][kk], kf[ni]);
                mma_f16(sacc[1][ni], qf[1][kk], kf[ni]);
            }
        }

        // softmax (log2 domain): max, then P fragments via f16x2 ex2
        uint32_t pfs[2][4][4];
#pragma unroll
        for (int b = 0; b < 2; b++) {
            float mx0 = -1e30f, mx1 = -1e30f;
#pragma unroll
            for (int ni = 0; ni < 8; ni++) {
                mx0 = fmaxf(mx0, fmaxf(sacc[b][ni][0], sacc[b][ni][1]));
                mx1 = fmaxf(mx1, fmaxf(sacc[b][ni][2], sacc[b][ni][3]));
            }
#pragma unroll
            for (int off = 1; off <= 2; off <<= 1) {
                mx0 = fmaxf(mx0, __shfl_xor_sync(0xffffffffu, mx0, off));
                mx1 = fmaxf(mx1, __shfl_xor_sync(0xffffffffu, mx1, off));
            }
            float mn0 = fmaxf(mrow[b][0], mx0), mn1 = fmaxf(mrow[b][1], mx1);
            float corr0 = exp2f(mrow[b][0] - mn0), corr1 = exp2f(mrow[b][1] - mn1);
            mrow[b][0] = mn0; mrow[b][1] = mn1;
#pragma unroll
            for (int kk = 0; kk < 4; kk++) {
                pfs[b][kk][0] = exp2_h2(sacc[b][2 * kk][0] - mn0,     sacc[b][2 * kk][1] - mn0);
                pfs[b][kk][1] = exp2_h2(sacc[b][2 * kk][2] - mn1,     sacc[b][2 * kk][3] - mn1);
                pfs[b][kk][2] = exp2_h2(sacc[b][2 * kk + 1][0] - mn0, sacc[b][2 * kk + 1][1] - mn0);
                pfs[b][kk][3] = exp2_h2(sacc[b][2 * kk + 1][2] - mn1, sacc[b][2 * kk + 1][3] - mn1);
            }
            lacc[b][0] *= corr0; lacc[b][1] *= corr0;
            lacc[b][2] *= corr1; lacc[b][3] *= corr1;
#pragma unroll
            for (int ni = 0; ni < 8; ni++) {
                oacc[b][ni][0] *= corr0; oacc[b][ni][1] *= corr0;
                oacc[b][ni][2] *= corr1; oacc[b][ni][3] *= corr1;
            }
        }

        // O += P V; l += P @ 1. V B-frags via trans ldmatrix from [key][dim].
#pragma unroll
        for (int kk = 0; kk < 4; kk++) {
            uint32_t vf[8][2];
#pragma unroll
            for (int nip = 0; nip < 4; nip++)
                LDMX4T(vf[2 * nip][0], vf[2 * nip][1], vf[2 * nip + 1][0], vf[2 * nip + 1][1],
                       vb + vt_off + (uint32_t)((kk * 16 * KSTRB + nip * 16) * 2));
#pragma unroll
            for (int b = 0; b < 2; b++) {
#pragma unroll
                for (int ni = 0; ni < 8; ni++)
                    mma_f16(oacc[b][ni], pfs[b][kk], vf[ni]);
                mma_f16(lacc[b], pfs[b][kk], onesb);
            }
        }
    }

    // write ctx [B,S,D] as fp16
    const int bb = bh >> 4;
    const int h  = bh & 15;
#pragma unroll
    for (int b = 0; b < 2; b++) {
        float inv0 = 1.0f / lacc[b][0];
        float inv1 = 1.0f / lacc[b][2];
        int s0 = q0 + wid * 32 + b * 16 + gid;
#pragma unroll
        for (int ni = 0; ni < 8; ni++) {
            int d = ni * 8 + 2 * tig;
            size_t base0 = ((size_t)bb * SS + s0) * DD + h * HDIM + d;
            size_t base1 = ((size_t)bb * SS + s0 + 8) * DD + h * HDIM + d;
            *reinterpret_cast<uint32_t*>(&g_ctxh[base0]) =
                pack_h16(oacc[b][ni][0] * inv0, oacc[b][ni][1] * inv0);
            *reinterpret_cast<uint32_t*>(&g_ctxh[base1]) =
                pack_h16(oacc[b][ni][2] * inv1, oacc[b][ni][3] * inv1);
        }
    }
}

// ---------------------------------------------------------------------------
// Kernel 4: RMS norm per row of g_x
// ---------------------------------------------------------------------------
__global__ __launch_bounds__(256) void rmsnorm_kernel(
    const float* __restrict__ scale, float* __restrict__ out)
{
    __shared__ float red[8];
    __shared__ float s_tot;
    const int row = blockIdx.x;
    const int tid = threadIdx.x;
    const float4* xr = reinterpret_cast<const float4*>(g_x + (size_t)row * DD);
    float4 xv = xr[tid];
    float ss = xv.x*xv.x + xv.y*xv.y + xv.z*xv.z + xv.w*xv.w;
#pragma unroll
    for (int off = 16; off > 0; off >>= 1)
        ss += __shfl_xor_sync(0xffffffffu, ss, off);
    if ((tid & 31) == 0) red[tid >> 5] = ss;
    __syncthreads();
    if (tid == 0) {
        float t = 0.f;
#pragma unroll
        for (int w = 0; w < 8; w++) t += red[w];
        s_tot = t;
    }
    __syncthreads();
    float rms = sqrtf(s_tot * (1.0f / DD));
    float inv = 1.0f / (rms + RMS_EPS);
    float4 sc = reinterpret_cast<const float4*>(scale)[tid];
    float4 ov;
    ov.x = xv.x * sc.x * inv;
    ov.y = xv.y * sc.y * inv;
    ov.z = xv.z * sc.z * inv;
    ov.w = xv.w * sc.w * inv;
    reinterpret_cast<float4*>(out)[(size_t)row * (DD / 4) + tid] = ov;
}

// ---------------------------------------------------------------------------
extern "C" void kernel_launch(void* const* d_in, const int* in_sizes, int n_in,
                              void* d_out, int out_size)
{
    const float* hidden = (const float*)d_in[0];
    const float* sinb   = (const float*)d_in[1];
    const float* cosb   = (const float*)d_in[2];
    const float* wq     = (const float*)d_in[3];
    const float* wk     = (const float*)d_in[4];
    const float* wv     = (const float*)d_in[5];
    const float* wo     = (const float*)d_in[6];
    const float* bo     = (const float*)d_in[7];
    const float* scale  = (const float*)d_in[8];
    float* out = (float*)d_out;

    const int n4h = MM * DD / 4;
    const int n4w = DD * DD / 4;
    cvt_h_kernel<<<(n4h + 255) / 256, 256>>>((const float4*)hidden);
    cvt_w_kernel<<<dim3((n4w + 255) / 256, 4), 256>>>(
        (const float4*)wq, (const float4*)wk, (const float4*)wv, (const float4*)wo);

    qkv_rope_mma_kernel<<<dim3(DD / 128, MM / 128, 3), 128>>>(sinb, cosb);
    attn_mma_kernel<<<dim3(SS / 128, BB * HH), 128>>>();
    oproj_mma_kernel<<<dim3(DD / 128, MM / 128), 128>>>(hidden, bo);
    rmsnorm_kernel<<<MM, 256>>>(scale, out);
}